// round 3
// baseline (speedup 1.0000x reference)
#include <cuda_runtime.h>

#define B_   4
#define C_   256
#define CR_  64
#define H_   64
#define W_   64
#define HW_  4096
#define KK_  49
#define G_   16
#define GC_  16

typedef unsigned long long u64;

// scratch for x = relu(bn(w1 @ guide)) : [B, CR, H, W]
__device__ float g_x[B_ * CR_ * HW_];

// ---------------- packed f32x2 helpers (sm_103a FFMA2 path) ----------------
__device__ __forceinline__ u64 pk2(float lo, float hi) {
    u64 r; asm("mov.b64 %0, {%1,%2};" : "=l"(r) : "f"(lo), "f"(hi)); return r;
}
__device__ __forceinline__ void upk2(u64 v, float& lo, float& hi) {
    asm("mov.b64 {%0,%1}, %2;" : "=f"(lo), "=f"(hi) : "l"(v));
}
__device__ __forceinline__ void fma2(u64& d, u64 a, u64 b) {
    asm("fma.rn.f32x2 %0, %1, %2, %0;" : "+l"(d) : "l"(a), "l"(b));
}
__device__ __forceinline__ u64 add2(u64 a, u64 b) {
    u64 r; asm("add.rn.f32x2 %0, %1, %2;" : "=l"(r) : "l"(a), "l"(b)); return r;
}

// ---------------------------------------------------------------------------
// Kernel 1: x[b,r,hw] = relu( inv[r]*(w1[r,:].guide[b,:,hw]) + bias[r] )
// block 256 thr -> 128 px x 64 r, f32x2 over pixel pairs. grid (32, B)
// ---------------------------------------------------------------------------
__global__ __launch_bounds__(256) void k1_compute_x(
    const float* __restrict__ guide,
    const float* __restrict__ w1,
    const float* __restrict__ gamma,
    const float* __restrict__ beta,
    const float* __restrict__ mean,
    const float* __restrict__ var)
{
    __shared__ float inv_s[CR_];
    __shared__ float bias_s[CR_];
    __shared__ float gtile[16][128];    // [c_chunk][px]
    __shared__ u64   w1t2[16 * CR_];    // [c_chunk][r], BN-folded, duplicated pair

    const int t    = threadIdx.x;
    const int b    = blockIdx.y;
    const int pix0 = blockIdx.x * 128;

    if (t < CR_) {
        float iv  = gamma[t] * rsqrtf(var[t] + 1e-5f);
        inv_s[t]  = iv;
        bias_s[t] = beta[t] - mean[t] * iv;
    }
    __syncthreads();

    const int L  = t & 31;    // pixel-pair lane: pairs {2L,2L+1} and {64+2L,...}
    const int rg = t >> 5;    // 8 r values

    u64 acc0[8], acc1[8];
    #pragma unroll
    for (int j = 0; j < 8; j++) { acc0[j] = 0ull; acc1[j] = 0ull; }

    for (int c0 = 0; c0 < C_; c0 += 16) {
        #pragma unroll
        for (int j = 0; j < 8; j++) {           // guide tile 16x128 coalesced
            int idx = t + 256 * j;
            int cc = idx >> 7, px = idx & 127;
            gtile[cc][px] = guide[(b * C_ + c0 + cc) * HW_ + pix0 + px];
        }
        #pragma unroll
        for (int j = 0; j < 4; j++) {           // w1 tile, coalesced over cc
            int idx = t + 256 * j;
            int cc = idx & 15, r = idx >> 4;
            float v = w1[r * C_ + c0 + cc] * inv_s[r];
            w1t2[cc * CR_ + r] = pk2(v, v);
        }
        __syncthreads();

        #pragma unroll 4
        for (int cc = 0; cc < 16; cc++) {
            u64 g0 = *(const u64*)&gtile[cc][2 * L];
            u64 g1 = *(const u64*)&gtile[cc][64 + 2 * L];
            const u64* wp = &w1t2[cc * CR_ + rg * 8];
            #pragma unroll
            for (int rr = 0; rr < 8; rr++) {
                u64 wv = wp[rr];                // broadcast LDS.64
                fma2(acc0[rr], wv, g0);
                fma2(acc1[rr], wv, g1);
            }
        }
        __syncthreads();
    }

    #pragma unroll
    for (int rr = 0; rr < 8; rr++) {
        int r = rg * 8 + rr;
        float bb = bias_s[r];
        float a, c, d, e;
        upk2(acc0[rr], a, c);
        upk2(acc1[rr], d, e);
        float2 v0 = make_float2(fmaxf(a + bb, 0.f), fmaxf(c + bb, 0.f));
        float2 v1 = make_float2(fmaxf(d + bb, 0.f), fmaxf(e + bb, 0.f));
        float* dst = &g_x[(b * CR_ + r) * HW_ + pix0];
        *(float2*)&dst[2 * L]      = v0;
        *(float2*)&dst[64 + 2 * L] = v1;
    }
}

// ---------------------------------------------------------------------------
// Kernel 2: fused dynamic-kernel GEMM + involution aggregation + residual.
// Block = one image ROW (64 px strip), 256 threads, loop over 16 groups.
// grid (64, B)
// ---------------------------------------------------------------------------

// dynamic smem layout (float indices)
#define XT_OFF    0                    // [64 r][64 px]                 4096
#define WSM_OFF   4096                 // [49 k][64 px] (k-major)       3136
#define FH_OFF    7232                 // [16 c][7 ky][72]              8064
#define B2S_OFF   15296                // [49]
#define W2G2_OFF  15346                // u64[49*64] duplicated pairs   (8B aligned)
#define SMEM2_FLOATS (15346 + 49 * 64 * 2)
#define SMEM2_BYTES  (SMEM2_FLOATS * 4)

__global__ __launch_bounds__(256) void k2_fused(
    const float* __restrict__ feat,
    const float* __restrict__ w2,
    const float* __restrict__ b2,
    float* __restrict__ out)
{
    extern __shared__ float sm[];
    float* xt   = sm + XT_OFF;
    float* wsm  = sm + WSM_OFF;
    float* fh   = sm + FH_OFF;
    float* b2s  = sm + B2S_OFF;
    u64*   w2g2 = (u64*)(sm + W2G2_OFF);

    const int t  = threadIdx.x;
    const int b  = blockIdx.y;
    const int y0 = blockIdx.x;

    // ---- load x strip: xt[r][px], coalesced 64-float rows ----
    #pragma unroll
    for (int j = 0; j < 16; j++) {
        int idx = t + 256 * j;
        int r = idx >> 6, px = idx & 63;
        xt[r * 64 + px] = g_x[(b * CR_ + r) * HW_ + y0 * W_ + px];
    }

    // phase-1 mapping: 4 px (2 pairs) x 3 k per thread (+ peeled tap 48)
    const int pxq = t & 15;
    const int k0  = 3 * (t >> 4);

    // phase-2 mapping: warp covers 8 px x 16 ch
    const int wid  = t >> 5;
    const int lane = t & 31;
    const int pb   = wid * 8 + 2 * (lane & 3);  // pixel pair base (even)
    const int cq   = lane >> 2;                 // channel pair 2cq, 2cq+1

    for (int g = 0; g < G_; g++) {
        // ---- w2 group slice -> duplicated pairs, k-major [k][r] ----
        #pragma unroll
        for (int j = 0; j < 13; j++) {
            int idx = t + 256 * j;
            if (idx < KK_ * CR_) {
                float v = w2[g * (KK_ * CR_) + idx];   // coalesced
                w2g2[idx] = pk2(v, v);                  // idx = k*64 + r
            }
        }
        if (t < KK_) b2s[t] = b2[g * KK_ + t];

        // ---- feature halo: 16 ch x 7 rows x 70 cols (stride 72) ----
        #pragma unroll
        for (int j = 0; j < 31; j++) {
            int idx = t + 256 * j;
            if (idx < 16 * 490) {
                int cc  = idx / 490;
                int rem = idx - cc * 490;
                int ky  = rem / 70;
                int ix  = rem - ky * 70;
                int gy = y0 + ky - 3, gx = ix - 3;
                float v = 0.f;
                if ((unsigned)gy < 64u && (unsigned)gx < 64u)
                    v = feat[(b * C_ + g * GC_ + cc) * HW_ + gy * W_ + gx];
                fh[cc * 504 + ky * 72 + ix] = v;
            }
        }
        __syncthreads();

        // ---- phase 1: wsm[k][px] = w2g . xt[:,px] + b2 (f32x2 over px) ----
        {
            u64 acc[3][2];
            #pragma unroll
            for (int j = 0; j < 3; j++) acc[j][0] = acc[j][1] = 0ull;

            const u64* wp = w2g2 + k0 * 64;
            #pragma unroll 4
            for (int r = 0; r < 64; r++) {
                ulonglong2 xv = *(const ulonglong2*)&xt[r * 64 + pxq * 4];
                u64 w0 = wp[r], w1v = wp[64 + r], w2v = wp[128 + r];
                fma2(acc[0][0], w0,  xv.x); fma2(acc[0][1], w0,  xv.y);
                fma2(acc[1][0], w1v, xv.x); fma2(acc[1][1], w1v, xv.y);
                fma2(acc[2][0], w2v, xv.x); fma2(acc[2][1], w2v, xv.y);
            }
            #pragma unroll
            for (int j = 0; j < 3; j++) {
                float bv = b2s[k0 + j];
                u64 bp = pk2(bv, bv);
                *(u64*)&wsm[(k0 + j) * 64 + pxq * 4]     = add2(acc[j][0], bp);
                *(u64*)&wsm[(k0 + j) * 64 + pxq * 4 + 2] = add2(acc[j][1], bp);
            }
            if (t < 64) {                      // peeled tap k = 48
                float a = 0.f;
                const float* wl = (const float*)(w2g2 + 48 * 64);
                #pragma unroll 8
                for (int r = 0; r < 64; r++)
                    a += wl[2 * r] * xt[r * 64 + t];
                wsm[48 * 64 + t] = a + b2s[48];
            }
        }
        __syncthreads();

        // ---- phase 2: per px-pair & channel pair, f32x2 over the 2 px ----
        {
            u64 oacc[2] = {0ull, 0ull};
            #pragma unroll
            for (int ky = 0; ky < 7; ky++) {
                u64 wk[7];
                #pragma unroll
                for (int kx = 0; kx < 7; kx++)            // dedup 4:1 in warp
                    wk[kx] = *(const u64*)&wsm[(ky * 7 + kx) * 64 + pb];
                #pragma unroll
                for (int c = 0; c < 2; c++) {
                    const float* frow = &fh[(2 * cq + c) * 504 + ky * 72 + pb];
                    u64 f0 = *(const u64*)(frow);
                    u64 f1 = *(const u64*)(frow + 2);
                    u64 f2 = *(const u64*)(frow + 4);
                    u64 f3 = *(const u64*)(frow + 6);
                    float e0, e1, e2, e3, e4, e5, e6, e7;
                    upk2(f0, e0, e1); upk2(f1, e2, e3);
                    upk2(f2, e4, e5); upk2(f3, e6, e7);
                    u64 ep1 = pk2(e1, e2);
                    u64 ep3 = pk2(e3, e4);
                    u64 ep5 = pk2(e5, e6);
                    fma2(oacc[c], wk[0], f0);
                    fma2(oacc[c], wk[1], ep1);
                    fma2(oacc[c], wk[2], f1);
                    fma2(oacc[c], wk[3], ep3);
                    fma2(oacc[c], wk[4], f2);
                    fma2(oacc[c], wk[5], ep5);
                    fma2(oacc[c], wk[6], f3);
                }
            }
            #pragma unroll
            for (int c = 0; c < 2; c++) {
                int cl = 2 * cq + c;
                int ch = g * GC_ + cl;
                float r0 = fh[cl * 504 + 3 * 72 + pb + 3];
                float r1 = fh[cl * 504 + 3 * 72 + pb + 4];
                float lo, hi;
                upk2(oacc[c], lo, hi);
                float2 v = make_float2(lo + r0, hi + r1);
                *(float2*)&out[(b * C_ + ch) * HW_ + y0 * W_ + pb] = v;
            }
        }
        __syncthreads();   // protect smem before next group
    }
}

// ---------------------------------------------------------------------------
extern "C" void kernel_launch(void* const* d_in, const int* in_sizes, int n_in,
                              void* d_out, int out_size)
{
    const float* feat  = (const float*)d_in[0];
    const float* guide = (const float*)d_in[1];
    const float* w1    = (const float*)d_in[2];
    const float* gamma = (const float*)d_in[3];
    const float* beta  = (const float*)d_in[4];
    const float* mean  = (const float*)d_in[5];
    const float* var   = (const float*)d_in[6];
    const float* w2    = (const float*)d_in[7];
    const float* b2    = (const float*)d_in[8];
    float* out = (float*)d_out;

    cudaFuncSetAttribute(k2_fused,
                         cudaFuncAttributeMaxDynamicSharedMemorySize,
                         SMEM2_BYTES);

    k1_compute_x<<<dim3(32, B_), 256>>>(guide, w1, gamma, beta, mean, var);
    k2_fused<<<dim3(64, B_), 256, SMEM2_BYTES>>>(feat, w2, b2, out);
}

// round 4
// speedup vs baseline: 1.3294x; 1.3294x over previous
#include <cuda_runtime.h>

#define B_   4
#define C_   256
#define CR_  64
#define H_   64
#define W_   64
#define HW_  4096
#define KK_  49
#define G_   16
#define GC_  16

typedef unsigned long long u64;

// scratch for x = relu(bn(w1 @ guide)) : [B, CR, H, W]
__device__ float g_x[B_ * CR_ * HW_];

// ---------------- packed f32x2 helpers (sm_103a FFMA2 path) ----------------
__device__ __forceinline__ u64 pk2(float lo, float hi) {
    u64 r; asm("mov.b64 %0, {%1,%2};" : "=l"(r) : "f"(lo), "f"(hi)); return r;
}
__device__ __forceinline__ void upk2(u64 v, float& lo, float& hi) {
    asm("mov.b64 {%0,%1}, %2;" : "=f"(lo), "=f"(hi) : "l"(v));
}
__device__ __forceinline__ void fma2(u64& d, u64 a, u64 b) {
    asm("fma.rn.f32x2 %0, %1, %2, %0;" : "+l"(d) : "l"(a), "l"(b));
}
__device__ __forceinline__ u64 add2(u64 a, u64 b) {
    u64 r; asm("add.rn.f32x2 %0, %1, %2;" : "=l"(r) : "l"(a), "l"(b)); return r;
}

// ---------------------------------------------------------------------------
// Kernel 1 (validated R2, ~12us): x = relu(bn(w1 @ guide)), f32x2 over px pairs
// ---------------------------------------------------------------------------
__global__ __launch_bounds__(256) void k1_compute_x(
    const float* __restrict__ guide,
    const float* __restrict__ w1,
    const float* __restrict__ gamma,
    const float* __restrict__ beta,
    const float* __restrict__ mean,
    const float* __restrict__ var)
{
    __shared__ float inv_s[CR_];
    __shared__ float bias_s[CR_];
    __shared__ float gtile[16][128];
    __shared__ u64   w1t2[16 * CR_];

    const int t    = threadIdx.x;
    const int b    = blockIdx.y;
    const int pix0 = blockIdx.x * 128;

    if (t < CR_) {
        float iv  = gamma[t] * rsqrtf(var[t] + 1e-5f);
        inv_s[t]  = iv;
        bias_s[t] = beta[t] - mean[t] * iv;
    }
    __syncthreads();

    const int L  = t & 31;
    const int rg = t >> 5;

    u64 acc0[8], acc1[8];
    #pragma unroll
    for (int j = 0; j < 8; j++) { acc0[j] = 0ull; acc1[j] = 0ull; }

    for (int c0 = 0; c0 < C_; c0 += 16) {
        #pragma unroll
        for (int j = 0; j < 8; j++) {
            int idx = t + 256 * j;
            int cc = idx >> 7, px = idx & 127;
            gtile[cc][px] = guide[(b * C_ + c0 + cc) * HW_ + pix0 + px];
        }
        #pragma unroll
        for (int j = 0; j < 4; j++) {
            int idx = t + 256 * j;
            int cc = idx & 15, r = idx >> 4;
            float v = w1[r * C_ + c0 + cc] * inv_s[r];
            w1t2[cc * CR_ + r] = pk2(v, v);
        }
        __syncthreads();

        #pragma unroll 4
        for (int cc = 0; cc < 16; cc++) {
            u64 g0 = *(const u64*)&gtile[cc][2 * L];
            u64 g1 = *(const u64*)&gtile[cc][64 + 2 * L];
            const u64* wp = &w1t2[cc * CR_ + rg * 8];
            #pragma unroll
            for (int rr = 0; rr < 8; rr++) {
                u64 wv = wp[rr];
                fma2(acc0[rr], wv, g0);
                fma2(acc1[rr], wv, g1);
            }
        }
        __syncthreads();
    }

    #pragma unroll
    for (int rr = 0; rr < 8; rr++) {
        int r = rg * 8 + rr;
        float bb = bias_s[r];
        float a, c, d, e;
        upk2(acc0[rr], a, c);
        upk2(acc1[rr], d, e);
        float2 v0 = make_float2(fmaxf(a + bb, 0.f), fmaxf(c + bb, 0.f));
        float2 v1 = make_float2(fmaxf(d + bb, 0.f), fmaxf(e + bb, 0.f));
        float* dst = &g_x[(b * CR_ + r) * HW_ + pix0];
        *(float2*)&dst[2 * L]      = v0;
        *(float2*)&dst[64 + 2 * L] = v1;
    }
}

// ---------------------------------------------------------------------------
// Kernel 2: 8x8 pixel tile, 4 groups per block, grid (8, 8, B*4).
// Phase 1 f32x2 GEMM -> wsm (k-major); phase 2 scalar aggregation.
// ---------------------------------------------------------------------------

// smem layout (float indices)
#define XT_OFF    0                       // [64 r][64 px]      4096
#define WSM_OFF   4096                    // [49 k][66 px pad]  3234
#define FH_OFF    7330                    // [16 c][14][16]     3584
#define B2S_OFF   10914                   // [49] (+pad)        50
#define W2G2_OFF  10964                   // u64[49*64] dup     6272 floats
#define SMEM2_FLOATS (10964 + 6272)
#define SMEM2_BYTES  (SMEM2_FLOATS * 4)   // 68944 B

__global__ __launch_bounds__(256) void k2_fused(
    const float* __restrict__ feat,
    const float* __restrict__ w2,
    const float* __restrict__ b2,
    float* __restrict__ out)
{
    extern __shared__ float sm[];
    float* xt   = sm + XT_OFF;
    float* wsm  = sm + WSM_OFF;
    float* fh   = sm + FH_OFF;
    float* b2s  = sm + B2S_OFF;
    u64*   w2g2 = (u64*)(sm + W2G2_OFF);

    const int t   = threadIdx.x;
    const int b   = blockIdx.z >> 2;
    const int gh  = blockIdx.z & 3;      // group chunk: groups gh*4 .. gh*4+3
    const int tx0 = blockIdx.x * 8;
    const int ty0 = blockIdx.y * 8;

    // ---- load x tile: xt[r][p], p = py*8 + px ----
    #pragma unroll
    for (int j = 0; j < 16; j++) {
        int idx = t + 256 * j;
        int r = idx >> 6, p = idx & 63;
        xt[r * 64 + p] =
            g_x[(b * CR_ + r) * HW_ + (ty0 + (p >> 3)) * W_ + tx0 + (p & 7)];
    }

    // phase-1 mapping: 4 px x 3 k per thread (+ peeled tap 48)
    const int pxq = t & 15;
    const int k0  = 3 * (t >> 4);

    // phase-2 mapping: 1 pixel-pair x 2 channels per thread
    const int p2  = t & 31;
    const int cp  = t >> 5;
    const int pb  = 2 * p2;              // tile pixel pair base (even)
    const int py  = pb >> 3;
    const int pxx = pb & 7;

    for (int gi = 0; gi < 4; gi++) {
        const int g = gh * 4 + gi;

        // ---- w2 group slice -> duplicated u64 pairs, [k][r] ----
        #pragma unroll
        for (int j = 0; j < 13; j++) {
            int idx = t + 256 * j;
            if (idx < KK_ * CR_) {
                float v = w2[g * (KK_ * CR_) + idx];   // coalesced
                w2g2[idx] = pk2(v, v);                 // idx = k*64 + r
            }
        }
        if (t < KK_) b2s[t] = b2[g * KK_ + t];

        // ---- feature halo: 16 ch x 14 x 14 (stride 16, zero-pad) ----
        #pragma unroll
        for (int j = 0; j < 13; j++) {
            int idx = t + 256 * j;
            if (idx < 16 * 196) {
                int cc  = idx / 196;
                int r2  = idx - cc * 196;
                int iy  = r2 / 14, ix = r2 - iy * 14;
                int gy = ty0 + iy - 3, gx = tx0 + ix - 3;
                float v = 0.f;
                if ((unsigned)gy < 64u && (unsigned)gx < 64u)
                    v = feat[(b * C_ + g * GC_ + cc) * HW_ + gy * W_ + gx];
                fh[cc * 224 + iy * 16 + ix] = v;
            }
        }
        __syncthreads();

        // ---- phase 1: wsm[k][px] = w2g . xt[:,px] + b2  (f32x2 over px) ----
        {
            u64 acc[3][2];
            #pragma unroll
            for (int j = 0; j < 3; j++) acc[j][0] = acc[j][1] = 0ull;

            const u64* wp0 = w2g2 + (k0 + 0) * 64;
            const u64* wp1 = w2g2 + (k0 + 1) * 64;
            const u64* wp2 = w2g2 + (k0 + 2) * 64;

            #pragma unroll 2
            for (int r = 0; r < 64; r += 2) {
                ulonglong2 xv0 = *(const ulonglong2*)&xt[r * 64 + pxq * 4];
                ulonglong2 xv1 = *(const ulonglong2*)&xt[(r + 1) * 64 + pxq * 4];
                ulonglong2 wa = *(const ulonglong2*)&wp0[r];  // broadcast LDS.128
                ulonglong2 wb = *(const ulonglong2*)&wp1[r];
                ulonglong2 wc = *(const ulonglong2*)&wp2[r];
                fma2(acc[0][0], wa.x, xv0.x); fma2(acc[0][1], wa.x, xv0.y);
                fma2(acc[1][0], wb.x, xv0.x); fma2(acc[1][1], wb.x, xv0.y);
                fma2(acc[2][0], wc.x, xv0.x); fma2(acc[2][1], wc.x, xv0.y);
                fma2(acc[0][0], wa.y, xv1.x); fma2(acc[0][1], wa.y, xv1.y);
                fma2(acc[1][0], wb.y, xv1.x); fma2(acc[1][1], wb.y, xv1.y);
                fma2(acc[2][0], wc.y, xv1.x); fma2(acc[2][1], wc.y, xv1.y);
            }
            #pragma unroll
            for (int j = 0; j < 3; j++) {
                float bv = b2s[k0 + j];
                u64 bp = pk2(bv, bv);
                *(u64*)&wsm[(k0 + j) * 66 + pxq * 4]     = add2(acc[j][0], bp);
                *(u64*)&wsm[(k0 + j) * 66 + pxq * 4 + 2] = add2(acc[j][1], bp);
            }
            if (t < 64) {                         // peeled tap k = 48
                float a = 0.f;
                const float* wl = (const float*)(w2g2 + 48 * 64);
                #pragma unroll 8
                for (int r = 0; r < 64; r++)
                    a += wl[2 * r] * xt[r * 64 + t];
                wsm[48 * 66 + t] = a + b2s[48];
            }
        }
        __syncthreads();

        // ---- phase 2: out[px][c] = sum_k w[px][k] * fh[c][py+ky][pxx+kx] ----
        {
            float oacc[2][2] = {{0.f, 0.f}, {0.f, 0.f}};
            #pragma unroll
            for (int ky = 0; ky < 7; ky++) {
                float wk0[7], wk1[7];
                #pragma unroll
                for (int kx = 0; kx < 7; kx++) {
                    u64 wv = *(const u64*)&wsm[(ky * 7 + kx) * 66 + pb];
                    upk2(wv, wk0[kx], wk1[kx]);
                }
                #pragma unroll
                for (int c = 0; c < 2; c++) {
                    const float* frow =
                        &fh[(cp * 2 + c) * 224 + (py + ky) * 16 + pxx];
                    float2 f0 = *(const float2*)(frow);
                    float2 f1 = *(const float2*)(frow + 2);
                    float2 f2 = *(const float2*)(frow + 4);
                    float2 f3 = *(const float2*)(frow + 6);
                    float e[8] = {f0.x, f0.y, f1.x, f1.y,
                                  f2.x, f2.y, f3.x, f3.y};
                    #pragma unroll
                    for (int kx = 0; kx < 7; kx++) {
                        oacc[0][c] += wk0[kx] * e[kx];
                        oacc[1][c] += wk1[kx] * e[kx + 1];
                    }
                }
            }
            #pragma unroll
            for (int c = 0; c < 2; c++) {
                int cc = cp * 2 + c;
                int ch = g * GC_ + cc;
                float v0 = oacc[0][c] + fh[cc * 224 + (py + 3) * 16 + (pxx + 3)];
                float v1 = oacc[1][c] + fh[cc * 224 + (py + 3) * 16 + (pxx + 4)];
                *(float2*)&out[(b * C_ + ch) * HW_ + (ty0 + py) * W_ + tx0 + pxx] =
                    make_float2(v0, v1);
            }
        }
        __syncthreads();   // protect smem before next group
    }
}

// ---------------------------------------------------------------------------
extern "C" void kernel_launch(void* const* d_in, const int* in_sizes, int n_in,
                              void* d_out, int out_size)
{
    const float* feat  = (const float*)d_in[0];
    const float* guide = (const float*)d_in[1];
    const float* w1    = (const float*)d_in[2];
    const float* gamma = (const float*)d_in[3];
    const float* beta  = (const float*)d_in[4];
    const float* mean  = (const float*)d_in[5];
    const float* var   = (const float*)d_in[6];
    const float* w2    = (const float*)d_in[7];
    const float* b2    = (const float*)d_in[8];
    float* out = (float*)d_out;

    cudaFuncSetAttribute(k2_fused,
                         cudaFuncAttributeMaxDynamicSharedMemorySize,
                         SMEM2_BYTES);

    k1_compute_x<<<dim3(32, B_), 256>>>(guide, w1, gamma, beta, mean, var);
    k2_fused<<<dim3(8, 8, B_ * 4), 256, SMEM2_BYTES>>>(feat, w2, b2, out);
}